// round 4
// baseline (speedup 1.0000x reference)
#include <cuda_runtime.h>
#include <math.h>

#define BB 4
#define SS 4096
#define NSTR 4
#define DD 1024
#define ND (NSTR * DD)            // 4096 floats per (b,s)
#define ND4 (ND / 4)              // 1024 float4 per (b,s)
#define D4 (DD / 4)               // 256 float4 per stream row
#define NCOLS 24
#define SCHUNKS 32
#define SPERCHUNK (SS / SCHUNKS)  // 128

// Scratch (allocation-free rule: __device__ globals)
__device__ float g_partial[BB][SCHUNKS][ND];   // 2 MB
__device__ float g_gates[BB][24];              // pre[4], post[4], res P[16]

// ---------------------------------------------------------------------------
// Kernel 1: partial sums of H over S. float4-vectorized.
// Default (evict-normal) loads: trailing ~126MB of H stays L2-resident for
// k_mix's re-read.
// ---------------------------------------------------------------------------
__global__ void __launch_bounds__(256) k_reduce(const float4* __restrict__ H4) {
    const int b     = blockIdx.z;
    const int chunk = blockIdx.y;
    const int col4  = blockIdx.x * 256 + threadIdx.x;  // 0..ND4-1
    const float4* base = H4 + ((size_t)b * SS + (size_t)chunk * SPERCHUNK) * ND4 + col4;
    float4 acc = make_float4(0.f, 0.f, 0.f, 0.f);
#pragma unroll 16
    for (int s = 0; s < SPERCHUNK; s++) {
        const float4 v = base[(size_t)s * ND4];   // evict-normal -> protected set
        acc.x += v.x; acc.y += v.y; acc.z += v.z; acc.w += v.w;
    }
    ((float4*)&g_partial[b][chunk][0])[col4] = acc;
}

// ---------------------------------------------------------------------------
// Kernel 2: finish mean, RMS-normalize, delta = x @ phi, gates + Sinkhorn.
// ---------------------------------------------------------------------------
__global__ void k_gates(const float* __restrict__ phi,
                        const float* __restrict__ pre_base,
                        const float* __restrict__ post_base,
                        const float* __restrict__ res_base,
                        const float* __restrict__ a_pre,
                        const float* __restrict__ a_post,
                        const float* __restrict__ a_res) {
    const int b    = blockIdx.x;
    const int tid  = threadIdx.x;
    const int lane = tid & 31;
    const int warp = tid >> 5;

    __shared__ float swarp[32];
    __shared__ float sred[32 * NCOLS];
    __shared__ float sdelta[NCOLS];
    __shared__ float s_invrms;

    float xloc[4];
#pragma unroll
    for (int r = 0; r < 4; r++) {
        const int c = tid + r * 1024;
        float acc = 0.0f;
#pragma unroll
        for (int ch = 0; ch < SCHUNKS; ch++) acc += g_partial[b][ch][c];
        xloc[r] = acc * (1.0f / (float)SS);
    }

    float ss = xloc[0] * xloc[0] + xloc[1] * xloc[1]
             + xloc[2] * xloc[2] + xloc[3] * xloc[3];
#pragma unroll
    for (int o = 16; o > 0; o >>= 1) ss += __shfl_down_sync(0xffffffffu, ss, o);
    if (lane == 0) swarp[warp] = ss;
    __syncthreads();
    if (tid == 0) {
        float t = 0.0f;
#pragma unroll
        for (int w = 0; w < 32; w++) t += swarp[w];
        s_invrms = 1.0f / sqrtf(t * (1.0f / (float)ND) + 1e-6f);
    }
    __syncthreads();
    const float invrms = s_invrms;

    float acc24[NCOLS];
#pragma unroll
    for (int j = 0; j < NCOLS; j++) acc24[j] = 0.0f;
#pragma unroll
    for (int r = 0; r < 4; r++) {
        const int c = tid + r * 1024;
        const float xv = xloc[r] * invrms;
        const float* ph = phi + (size_t)c * NCOLS;
#pragma unroll
        for (int j = 0; j < NCOLS; j++) acc24[j] += xv * ph[j];
    }
#pragma unroll
    for (int j = 0; j < NCOLS; j++) {
#pragma unroll
        for (int o = 16; o > 0; o >>= 1)
            acc24[j] += __shfl_down_sync(0xffffffffu, acc24[j], o);
    }
    if (lane == 0) {
#pragma unroll
        for (int j = 0; j < NCOLS; j++) sred[warp * NCOLS + j] = acc24[j];
    }
    __syncthreads();
    if (tid < NCOLS) {
        float t = 0.0f;
#pragma unroll
        for (int w = 0; w < 32; w++) t += sred[w * NCOLS + tid];
        sdelta[tid] = t;
    }
    __syncthreads();

    if (tid == 0) {
        const float ap  = *a_pre;
        const float apo = *a_post;
        const float ar  = *a_res;

        float pre[4];
        float psum = 0.0f;
#pragma unroll
        for (int k = 0; k < 4; k++) {
            pre[k] = 1.0f / (1.0f + expf(-(pre_base[k] + ap * sdelta[k])));
            psum += pre[k];
        }
        const float pinv = 1.0f / (psum + 1e-8f);
#pragma unroll
        for (int k = 0; k < 4; k++) g_gates[b][k] = pre[k] * pinv;

#pragma unroll
        for (int k = 0; k < 4; k++)
            g_gates[b][4 + k] = 1.0f / (1.0f + expf(-(post_base[k] + apo * sdelta[4 + k])));

        float P[16];
#pragma unroll
        for (int t = 0; t < 16; t++)
            P[t] = expf(res_base[t] + ar * sdelta[8 + t]);
        for (int it = 0; it < 20; it++) {
#pragma unroll
            for (int i = 0; i < 4; i++) {
                const float rs = P[i * 4 + 0] + P[i * 4 + 1] + P[i * 4 + 2] + P[i * 4 + 3];
                const float inv = 1.0f / (rs + 1e-6f);
                P[i * 4 + 0] *= inv; P[i * 4 + 1] *= inv;
                P[i * 4 + 2] *= inv; P[i * 4 + 3] *= inv;
            }
#pragma unroll
            for (int j = 0; j < 4; j++) {
                const float cs = P[0 * 4 + j] + P[1 * 4 + j] + P[2 * 4 + j] + P[3 * 4 + j];
                const float inv = 1.0f / (cs + 1e-6f);
                P[0 * 4 + j] *= inv; P[1 * 4 + j] *= inv;
                P[2 * 4 + j] *= inv; P[3 * 4 + j] *= inv;
            }
        }
#pragma unroll
        for (int t = 0; t < 16; t++) g_gates[b][8 + t] = P[t];
    }
}

// ---------------------------------------------------------------------------
// Kernel 3: streaming mix. One block per TWO (b,s) rows; 256 threads.
// H/bo loads .cs (hits demote, misses allocate evict-first -> no pollution of
// the hot H set); output stores __stwt (write-through, NO L2 allocation).
// ---------------------------------------------------------------------------
__global__ void __launch_bounds__(256) k_mix(const float* __restrict__ H,
                                             const float* __restrict__ bo,
                                             float* __restrict__ out) {
    const int bs0 = blockIdx.x * 2;
    const int bs1 = bs0 + 1;
    const int b   = bs0 >> 12;          // /4096
    const int d4  = threadIdx.x;        // 0..255

    __shared__ float g[24];
    if (threadIdx.x < 24) g[threadIdx.x] = g_gates[b][threadIdx.x];

    const float4* hA = (const float4*)(H + (size_t)bs0 * ND);
    const float4* hB = (const float4*)(H + (size_t)bs1 * ND);

    const float4 a0 = __ldcs(hA + 0 * D4 + d4);
    const float4 a1 = __ldcs(hA + 1 * D4 + d4);
    const float4 a2 = __ldcs(hA + 2 * D4 + d4);
    const float4 a3 = __ldcs(hA + 3 * D4 + d4);
    const float4 av = __ldcs((const float4*)(bo + (size_t)bs0 * DD) + d4);
    const float4 b0 = __ldcs(hB + 0 * D4 + d4);
    const float4 b1 = __ldcs(hB + 1 * D4 + d4);
    const float4 b2 = __ldcs(hB + 2 * D4 + d4);
    const float4 b3 = __ldcs(hB + 3 * D4 + d4);
    const float4 bv = __ldcs((const float4*)(bo + (size_t)bs1 * DD) + d4);

    __syncthreads();

    float4* oA = (float4*)(out + (size_t)bs0 * 5 * DD);
    float4* oB = (float4*)(out + (size_t)bs1 * 5 * DD);

    {
        float4 o;
        o.x = g[0]*a0.x + g[1]*a1.x + g[2]*a2.x + g[3]*a3.x;
        o.y = g[0]*a0.y + g[1]*a1.y + g[2]*a2.y + g[3]*a3.y;
        o.z = g[0]*a0.z + g[1]*a1.z + g[2]*a2.z + g[3]*a3.z;
        o.w = g[0]*a0.w + g[1]*a1.w + g[2]*a2.w + g[3]*a3.w;
        __stwt(oA + d4, o);
        o.x = g[0]*b0.x + g[1]*b1.x + g[2]*b2.x + g[3]*b3.x;
        o.y = g[0]*b0.y + g[1]*b1.y + g[2]*b2.y + g[3]*b3.y;
        o.z = g[0]*b0.z + g[1]*b1.z + g[2]*b2.z + g[3]*b3.z;
        o.w = g[0]*b0.w + g[1]*b1.w + g[2]*b2.w + g[3]*b3.w;
        __stwt(oB + d4, o);
    }

#pragma unroll
    for (int i = 0; i < 4; i++) {
        const float r0 = g[8 + i * 4 + 0];
        const float r1 = g[8 + i * 4 + 1];
        const float r2 = g[8 + i * 4 + 2];
        const float r3 = g[8 + i * 4 + 3];
        const float p  = g[4 + i];
        float4 o;
        o.x = r0*a0.x + r1*a1.x + r2*a2.x + r3*a3.x + p*av.x;
        o.y = r0*a0.y + r1*a1.y + r2*a2.y + r3*a3.y + p*av.y;
        o.z = r0*a0.z + r1*a1.z + r2*a2.z + r3*a3.z + p*av.z;
        o.w = r0*a0.w + r1*a1.w + r2*a2.w + r3*a3.w + p*av.w;
        __stwt(oA + (1 + i) * D4 + d4, o);
        o.x = r0*b0.x + r1*b1.x + r2*b2.x + r3*b3.x + p*bv.x;
        o.y = r0*b0.y + r1*b1.y + r2*b2.y + r3*b3.y + p*bv.y;
        o.z = r0*b0.z + r1*b1.z + r2*b2.z + r3*b3.z + p*bv.z;
        o.w = r0*b0.w + r1*b1.w + r2*b2.w + r3*b3.w + p*bv.w;
        __stwt(oB + (1 + i) * D4 + d4, o);
    }
}

// ---------------------------------------------------------------------------
extern "C" void kernel_launch(void* const* d_in, const int* in_sizes, int n_in,
                              void* d_out, int out_size) {
    const float* H         = (const float*)d_in[0];
    const float* branch_o  = (const float*)d_in[1];
    const float* phi       = (const float*)d_in[2];
    const float* pre_base  = (const float*)d_in[3];
    const float* post_base = (const float*)d_in[4];
    const float* res_base  = (const float*)d_in[5];
    const float* a_pre     = (const float*)d_in[6];
    const float* a_post    = (const float*)d_in[7];
    const float* a_res     = (const float*)d_in[8];
    float* out = (float*)d_out;

    dim3 g1(ND4 / 256, SCHUNKS, BB);
    k_reduce<<<g1, 256>>>((const float4*)H);
    k_gates<<<BB, 1024>>>(phi, pre_base, post_base, res_base, a_pre, a_post, a_res);
    k_mix<<<BB * SS / 2, 256>>>(H, branch_o, out);
}

// round 5
// speedup vs baseline: 1.0172x; 1.0172x over previous
#include <cuda_runtime.h>
#include <math.h>

#define BB 4
#define SS 4096
#define NSTR 4
#define DD 1024
#define ND (NSTR * DD)            // 4096 floats per (b,s)
#define ND4 (ND / 4)              // 1024 float4 per (b,s)
#define D4 (DD / 4)               // 256 float4 per stream row
#define NCOLS 24
#define SCHUNKS 32
#define SPERCHUNK (SS / SCHUNKS)  // 128

// Scratch (allocation-free rule: __device__ globals)
__device__ float g_partial[BB][SCHUNKS][ND];   // 2 MB
__device__ float g_gates[BB][24];              // pre[4], post[4], res P[16]

// ---------------------------------------------------------------------------
// Kernel 1: partial sums of H over S. float4-vectorized.
// Reads s DESCENDING within each chunk so the L2-resident set at kernel end
// is the HEAD half (s_local 0..~62) of every chunk -- exactly what
// k_mix(half=0) consumes first. Default (evict-normal) loads = protected set.
// ---------------------------------------------------------------------------
__global__ void __launch_bounds__(256) k_reduce(const float4* __restrict__ H4) {
    const int b     = blockIdx.z;
    const int chunk = blockIdx.y;
    const int col4  = blockIdx.x * 256 + threadIdx.x;  // 0..ND4-1
    const float4* base = H4 + ((size_t)b * SS + (size_t)chunk * SPERCHUNK) * ND4 + col4;
    float4 acc = make_float4(0.f, 0.f, 0.f, 0.f);
#pragma unroll 16
    for (int s = SPERCHUNK - 1; s >= 0; s--) {     // descending
        const float4 v = base[(size_t)s * ND4];    // evict-normal
        acc.x += v.x; acc.y += v.y; acc.z += v.z; acc.w += v.w;
    }
    ((float4*)&g_partial[b][chunk][0])[col4] = acc;
}

// ---------------------------------------------------------------------------
// Kernel 2: finish mean, RMS-normalize, delta = x @ phi, gates + Sinkhorn.
// ---------------------------------------------------------------------------
__global__ void k_gates(const float* __restrict__ phi,
                        const float* __restrict__ pre_base,
                        const float* __restrict__ post_base,
                        const float* __restrict__ res_base,
                        const float* __restrict__ a_pre,
                        const float* __restrict__ a_post,
                        const float* __restrict__ a_res) {
    const int b    = blockIdx.x;
    const int tid  = threadIdx.x;
    const int lane = tid & 31;
    const int warp = tid >> 5;

    __shared__ float swarp[32];
    __shared__ float sred[32 * NCOLS];
    __shared__ float sdelta[NCOLS];
    __shared__ float s_invrms;

    float xloc[4];
#pragma unroll
    for (int r = 0; r < 4; r++) {
        const int c = tid + r * 1024;
        float acc = 0.0f;
#pragma unroll
        for (int ch = 0; ch < SCHUNKS; ch++) acc += g_partial[b][ch][c];
        xloc[r] = acc * (1.0f / (float)SS);
    }

    float ss = xloc[0] * xloc[0] + xloc[1] * xloc[1]
             + xloc[2] * xloc[2] + xloc[3] * xloc[3];
#pragma unroll
    for (int o = 16; o > 0; o >>= 1) ss += __shfl_down_sync(0xffffffffu, ss, o);
    if (lane == 0) swarp[warp] = ss;
    __syncthreads();
    if (tid == 0) {
        float t = 0.0f;
#pragma unroll
        for (int w = 0; w < 32; w++) t += swarp[w];
        s_invrms = 1.0f / sqrtf(t * (1.0f / (float)ND) + 1e-6f);
    }
    __syncthreads();
    const float invrms = s_invrms;

    float acc24[NCOLS];
#pragma unroll
    for (int j = 0; j < NCOLS; j++) acc24[j] = 0.0f;
#pragma unroll
    for (int r = 0; r < 4; r++) {
        const int c = tid + r * 1024;
        const float xv = xloc[r] * invrms;
        const float* ph = phi + (size_t)c * NCOLS;
#pragma unroll
        for (int j = 0; j < NCOLS; j++) acc24[j] += xv * ph[j];
    }
#pragma unroll
    for (int j = 0; j < NCOLS; j++) {
#pragma unroll
        for (int o = 16; o > 0; o >>= 1)
            acc24[j] += __shfl_down_sync(0xffffffffu, acc24[j], o);
    }
    if (lane == 0) {
#pragma unroll
        for (int j = 0; j < NCOLS; j++) sred[warp * NCOLS + j] = acc24[j];
    }
    __syncthreads();
    if (tid < NCOLS) {
        float t = 0.0f;
#pragma unroll
        for (int w = 0; w < 32; w++) t += sred[w * NCOLS + tid];
        sdelta[tid] = t;
    }
    __syncthreads();

    if (tid == 0) {
        const float ap  = *a_pre;
        const float apo = *a_post;
        const float ar  = *a_res;

        float pre[4];
        float psum = 0.0f;
#pragma unroll
        for (int k = 0; k < 4; k++) {
            pre[k] = 1.0f / (1.0f + expf(-(pre_base[k] + ap * sdelta[k])));
            psum += pre[k];
        }
        const float pinv = 1.0f / (psum + 1e-8f);
#pragma unroll
        for (int k = 0; k < 4; k++) g_gates[b][k] = pre[k] * pinv;

#pragma unroll
        for (int k = 0; k < 4; k++)
            g_gates[b][4 + k] = 1.0f / (1.0f + expf(-(post_base[k] + apo * sdelta[4 + k])));

        float P[16];
#pragma unroll
        for (int t = 0; t < 16; t++)
            P[t] = expf(res_base[t] + ar * sdelta[8 + t]);
        for (int it = 0; it < 20; it++) {
#pragma unroll
            for (int i = 0; i < 4; i++) {
                const float rs = P[i * 4 + 0] + P[i * 4 + 1] + P[i * 4 + 2] + P[i * 4 + 3];
                const float inv = 1.0f / (rs + 1e-6f);
                P[i * 4 + 0] *= inv; P[i * 4 + 1] *= inv;
                P[i * 4 + 2] *= inv; P[i * 4 + 3] *= inv;
            }
#pragma unroll
            for (int j = 0; j < 4; j++) {
                const float cs = P[0 * 4 + j] + P[1 * 4 + j] + P[2 * 4 + j] + P[3 * 4 + j];
                const float inv = 1.0f / (cs + 1e-6f);
                P[0 * 4 + j] *= inv; P[1 * 4 + j] *= inv;
                P[2 * 4 + j] *= inv; P[3 * 4 + j] *= inv;
            }
        }
#pragma unroll
        for (int t = 0; t < 16; t++) g_gates[b][8 + t] = P[t];
    }
}

// ---------------------------------------------------------------------------
// Kernel 3: streaming mix over one HALF of every chunk.
// half=0 -> s_local 0..63 (the L2-resident halves, launched first)
// half=1 -> s_local 64..127 (cold halves)
// One block per TWO (b,s) rows; 256 threads. H/bo loads .cs, stores .cs.
// ---------------------------------------------------------------------------
__global__ void __launch_bounds__(256) k_mix(const float* __restrict__ H,
                                             const float* __restrict__ bo,
                                             float* __restrict__ out,
                                             const int half) {
    // blockIdx.x in [0, BB*SCHUNKS*32): pair(5b) | chunk(5b) | b(2b)
    const int idx   = blockIdx.x;
    const int pair  = idx & 31;          // 0..31 -> 2 rows each = 64 rows
    const int chunk = (idx >> 5) & 31;
    const int b     = idx >> 10;
    const int bs0   = b * SS + chunk * SPERCHUNK + half * 64 + pair * 2;
    const int bs1   = bs0 + 1;
    const int d4    = threadIdx.x;       // 0..255

    __shared__ float g[24];
    if (threadIdx.x < 24) g[threadIdx.x] = g_gates[b][threadIdx.x];

    const float4* hA = (const float4*)(H + (size_t)bs0 * ND);
    const float4* hB = (const float4*)(H + (size_t)bs1 * ND);

    const float4 a0 = __ldcs(hA + 0 * D4 + d4);
    const float4 a1 = __ldcs(hA + 1 * D4 + d4);
    const float4 a2 = __ldcs(hA + 2 * D4 + d4);
    const float4 a3 = __ldcs(hA + 3 * D4 + d4);
    const float4 av = __ldcs((const float4*)(bo + (size_t)bs0 * DD) + d4);
    const float4 b0 = __ldcs(hB + 0 * D4 + d4);
    const float4 b1 = __ldcs(hB + 1 * D4 + d4);
    const float4 b2 = __ldcs(hB + 2 * D4 + d4);
    const float4 b3 = __ldcs(hB + 3 * D4 + d4);
    const float4 bv = __ldcs((const float4*)(bo + (size_t)bs1 * DD) + d4);

    __syncthreads();

    float4* oA = (float4*)(out + (size_t)bs0 * 5 * DD);
    float4* oB = (float4*)(out + (size_t)bs1 * 5 * DD);

    {
        float4 o;
        o.x = g[0]*a0.x + g[1]*a1.x + g[2]*a2.x + g[3]*a3.x;
        o.y = g[0]*a0.y + g[1]*a1.y + g[2]*a2.y + g[3]*a3.y;
        o.z = g[0]*a0.z + g[1]*a1.z + g[2]*a2.z + g[3]*a3.z;
        o.w = g[0]*a0.w + g[1]*a1.w + g[2]*a2.w + g[3]*a3.w;
        __stcs(oA + d4, o);
        o.x = g[0]*b0.x + g[1]*b1.x + g[2]*b2.x + g[3]*b3.x;
        o.y = g[0]*b0.y + g[1]*b1.y + g[2]*b2.y + g[3]*b3.y;
        o.z = g[0]*b0.z + g[1]*b1.z + g[2]*b2.z + g[3]*b3.z;
        o.w = g[0]*b0.w + g[1]*b1.w + g[2]*b2.w + g[3]*b3.w;
        __stcs(oB + d4, o);
    }

#pragma unroll
    for (int i = 0; i < 4; i++) {
        const float r0 = g[8 + i * 4 + 0];
        const float r1 = g[8 + i * 4 + 1];
        const float r2 = g[8 + i * 4 + 2];
        const float r3 = g[8 + i * 4 + 3];
        const float p  = g[4 + i];
        float4 o;
        o.x = r0*a0.x + r1*a1.x + r2*a2.x + r3*a3.x + p*av.x;
        o.y = r0*a0.y + r1*a1.y + r2*a2.y + r3*a3.y + p*av.y;
        o.z = r0*a0.z + r1*a1.z + r2*a2.z + r3*a3.z + p*av.z;
        o.w = r0*a0.w + r1*a1.w + r2*a2.w + r3*a3.w + p*av.w;
        __stcs(oA + (1 + i) * D4 + d4, o);
        o.x = r0*b0.x + r1*b1.x + r2*b2.x + r3*b3.x + p*bv.x;
        o.y = r0*b0.y + r1*b1.y + r2*b2.y + r3*b3.y + p*bv.y;
        o.z = r0*b0.z + r1*b1.z + r2*b2.z + r3*b3.z + p*bv.z;
        o.w = r0*b0.w + r1*b1.w + r2*b2.w + r3*b3.w + p*bv.w;
        __stcs(oB + (1 + i) * D4 + d4, o);
    }
}

// ---------------------------------------------------------------------------
extern "C" void kernel_launch(void* const* d_in, const int* in_sizes, int n_in,
                              void* d_out, int out_size) {
    const float* H         = (const float*)d_in[0];
    const float* branch_o  = (const float*)d_in[1];
    const float* phi       = (const float*)d_in[2];
    const float* pre_base  = (const float*)d_in[3];
    const float* post_base = (const float*)d_in[4];
    const float* res_base  = (const float*)d_in[5];
    const float* a_pre     = (const float*)d_in[6];
    const float* a_post    = (const float*)d_in[7];
    const float* a_res     = (const float*)d_in[8];
    float* out = (float*)d_out;

    dim3 g1(ND4 / 256, SCHUNKS, BB);
    k_reduce<<<g1, 256>>>((const float4*)H);
    k_gates<<<BB, 1024>>>(phi, pre_base, post_base, res_base, a_pre, a_post, a_res);
    const int mix_grid = BB * SCHUNKS * 32;             // 4096 blocks per half
    k_mix<<<mix_grid, 256>>>(H, branch_o, out, 0);      // hot halves first
    k_mix<<<mix_grid, 256>>>(H, branch_o, out, 1);      // cold halves
}

// round 6
// speedup vs baseline: 1.1008x; 1.0822x over previous
#include <cuda_runtime.h>
#include <math.h>

#define BB 4
#define SS 4096
#define NSTR 4
#define DD 1024
#define ND (NSTR * DD)            // 4096 floats per (b,s)
#define ND4 (ND / 4)              // 1024 float4 per (b,s)
#define D4 (DD / 4)               // 256 float4 per stream row
#define NCOLS 24
#define SCHUNKS 32
#define SPERCHUNK (SS / SCHUNKS)  // 128
#define GA_BLOCKS 16              // col-blocks per batch in k_gA
#define GA_COLS 256               // columns per k_gA block

// Scratch (allocation-free rule: __device__ globals)
__device__ float g_partial[BB][SCHUNKS][ND];       // 2 MB
__device__ float g_dpart[BB][GA_BLOCKS][NCOLS];    // per-block 24-dot partials
__device__ float g_ssp[BB][GA_BLOCKS];             // per-block sum-of-squares
__device__ float g_gates[BB][24];                  // pre[4], post[4], P[16]

// ---------------------------------------------------------------------------
// Kernel 1: partial sums of H over S. float4-vectorized, s DESCENDING so the
// L2-resident set at kernel end is the HEAD half of every chunk (what
// k_mix(half=0) consumes). Default evict-normal loads = protected set.
// ---------------------------------------------------------------------------
__global__ void __launch_bounds__(256) k_reduce(const float4* __restrict__ H4) {
    const int b     = blockIdx.z;
    const int chunk = blockIdx.y;
    const int col4  = blockIdx.x * 256 + threadIdx.x;  // 0..ND4-1
    const float4* base = H4 + ((size_t)b * SS + (size_t)chunk * SPERCHUNK) * ND4 + col4;
    float4 acc = make_float4(0.f, 0.f, 0.f, 0.f);
#pragma unroll 16
    for (int s = SPERCHUNK - 1; s >= 0; s--) {
        const float4 v = base[(size_t)s * ND4];
        acc.x += v.x; acc.y += v.y; acc.z += v.z; acc.w += v.w;
    }
    ((float4*)&g_partial[b][chunk][0])[col4] = acc;
}

// ---------------------------------------------------------------------------
// Kernel 2a: parallel gate reductions. grid (GA_BLOCKS, BB), 256 threads.
// Each block: 256 columns of batch b. Finishes the chunk reduction -> x,
// accumulates ss = sum x^2 and the 24 dots d_j = sum_c x_c * phi[c][j]
// (invrms applied later -- it factors out).
// ---------------------------------------------------------------------------
__global__ void __launch_bounds__(256) k_gA(const float* __restrict__ phi) {
    const int b    = blockIdx.y;
    const int cblk = blockIdx.x;
    const int tid  = threadIdx.x;
    const int lane = tid & 31;
    const int warp = tid >> 5;            // 0..7
    const int col  = cblk * GA_COLS + tid;

    // finish mean over S for this column
    float x = 0.0f;
#pragma unroll
    for (int ch = 0; ch < SCHUNKS; ch++) x += g_partial[b][ch][col];
    x *= (1.0f / (float)SS);

    // 24 dots + sum of squares
    float acc24[NCOLS];
    const float* ph = phi + (size_t)col * NCOLS;
#pragma unroll
    for (int j = 0; j < NCOLS; j++) acc24[j] = x * ph[j];
    float ss = x * x;

    // warp reduce
#pragma unroll
    for (int o = 16; o > 0; o >>= 1) {
        ss += __shfl_down_sync(0xffffffffu, ss, o);
#pragma unroll
        for (int j = 0; j < NCOLS; j++)
            acc24[j] += __shfl_down_sync(0xffffffffu, acc24[j], o);
    }

    __shared__ float sred[8][NCOLS];
    __shared__ float sss[8];
    if (lane == 0) {
#pragma unroll
        for (int j = 0; j < NCOLS; j++) sred[warp][j] = acc24[j];
        sss[warp] = ss;
    }
    __syncthreads();
    if (tid < NCOLS) {
        float t = 0.0f;
#pragma unroll
        for (int w = 0; w < 8; w++) t += sred[w][tid];
        g_dpart[b][cblk][tid] = t;
    }
    if (tid == NCOLS) {
        float t = 0.0f;
#pragma unroll
        for (int w = 0; w < 8; w++) t += sss[w];
        g_ssp[b][cblk] = t;
    }
}

// ---------------------------------------------------------------------------
// Kernel 2b: combine partials + gates + Sinkhorn. 1 block, 4 warps (=4 batches).
// ---------------------------------------------------------------------------
__global__ void __launch_bounds__(128) k_gB(const float* __restrict__ pre_base,
                                            const float* __restrict__ post_base,
                                            const float* __restrict__ res_base,
                                            const float* __restrict__ a_pre,
                                            const float* __restrict__ a_post,
                                            const float* __restrict__ a_res) {
    const int b    = threadIdx.x >> 5;   // warp = batch
    const int lane = threadIdx.x & 31;

    __shared__ float sdelta[BB][NCOLS];

    // invrms on lane 0, broadcast
    float invrms = 0.0f;
    if (lane == 0) {
        float ssum = 0.0f;
#pragma unroll
        for (int k = 0; k < GA_BLOCKS; k++) ssum += g_ssp[b][k];
        invrms = 1.0f / sqrtf(ssum * (1.0f / (float)ND) + 1e-6f);
    }
    invrms = __shfl_sync(0xffffffffu, invrms, 0);

    if (lane < NCOLS) {
        float t = 0.0f;
#pragma unroll
        for (int k = 0; k < GA_BLOCKS; k++) t += g_dpart[b][k][lane];
        sdelta[b][lane] = t * invrms;
    }
    __syncwarp();

    if (lane == 0) {
        const float ap  = *a_pre;
        const float apo = *a_post;
        const float ar  = *a_res;

        float pre[4];
        float psum = 0.0f;
#pragma unroll
        for (int k = 0; k < 4; k++) {
            pre[k] = 1.0f / (1.0f + expf(-(pre_base[k] + ap * sdelta[b][k])));
            psum += pre[k];
        }
        const float pinv = 1.0f / (psum + 1e-8f);
#pragma unroll
        for (int k = 0; k < 4; k++) g_gates[b][k] = pre[k] * pinv;

#pragma unroll
        for (int k = 0; k < 4; k++)
            g_gates[b][4 + k] = 1.0f / (1.0f + expf(-(post_base[k] + apo * sdelta[b][4 + k])));

        float P[16];
#pragma unroll
        for (int t = 0; t < 16; t++)
            P[t] = expf(res_base[t] + ar * sdelta[b][8 + t]);
        for (int it = 0; it < 20; it++) {
#pragma unroll
            for (int i = 0; i < 4; i++) {
                const float rs = P[i * 4 + 0] + P[i * 4 + 1] + P[i * 4 + 2] + P[i * 4 + 3];
                const float inv = 1.0f / (rs + 1e-6f);
                P[i * 4 + 0] *= inv; P[i * 4 + 1] *= inv;
                P[i * 4 + 2] *= inv; P[i * 4 + 3] *= inv;
            }
#pragma unroll
            for (int j = 0; j < 4; j++) {
                const float cs = P[0 * 4 + j] + P[1 * 4 + j] + P[2 * 4 + j] + P[3 * 4 + j];
                const float inv = 1.0f / (cs + 1e-6f);
                P[0 * 4 + j] *= inv; P[1 * 4 + j] *= inv;
                P[2 * 4 + j] *= inv; P[3 * 4 + j] *= inv;
            }
        }
#pragma unroll
        for (int t = 0; t < 16; t++) g_gates[b][8 + t] = P[t];
    }
}

// ---------------------------------------------------------------------------
// Kernel 3: streaming mix over one HALF of every chunk.
// half=0 -> s_local 0..63 (L2-resident halves, launched first)
// half=1 -> s_local 64..127 (cold halves)
// ---------------------------------------------------------------------------
__global__ void __launch_bounds__(256) k_mix(const float* __restrict__ H,
                                             const float* __restrict__ bo,
                                             float* __restrict__ out,
                                             const int half) {
    const int idx   = blockIdx.x;
    const int pair  = idx & 31;
    const int chunk = (idx >> 5) & 31;
    const int b     = idx >> 10;
    const int bs0   = b * SS + chunk * SPERCHUNK + half * 64 + pair * 2;
    const int bs1   = bs0 + 1;
    const int d4    = threadIdx.x;

    __shared__ float g[24];
    if (threadIdx.x < 24) g[threadIdx.x] = g_gates[b][threadIdx.x];

    const float4* hA = (const float4*)(H + (size_t)bs0 * ND);
    const float4* hB = (const float4*)(H + (size_t)bs1 * ND);

    const float4 a0 = __ldcs(hA + 0 * D4 + d4);
    const float4 a1 = __ldcs(hA + 1 * D4 + d4);
    const float4 a2 = __ldcs(hA + 2 * D4 + d4);
    const float4 a3 = __ldcs(hA + 3 * D4 + d4);
    const float4 av = __ldcs((const float4*)(bo + (size_t)bs0 * DD) + d4);
    const float4 b0 = __ldcs(hB + 0 * D4 + d4);
    const float4 b1 = __ldcs(hB + 1 * D4 + d4);
    const float4 b2 = __ldcs(hB + 2 * D4 + d4);
    const float4 b3 = __ldcs(hB + 3 * D4 + d4);
    const float4 bv = __ldcs((const float4*)(bo + (size_t)bs1 * DD) + d4);

    __syncthreads();

    float4* oA = (float4*)(out + (size_t)bs0 * 5 * DD);
    float4* oB = (float4*)(out + (size_t)bs1 * 5 * DD);

    {
        float4 o;
        o.x = g[0]*a0.x + g[1]*a1.x + g[2]*a2.x + g[3]*a3.x;
        o.y = g[0]*a0.y + g[1]*a1.y + g[2]*a2.y + g[3]*a3.y;
        o.z = g[0]*a0.z + g[1]*a1.z + g[2]*a2.z + g[3]*a3.z;
        o.w = g[0]*a0.w + g[1]*a1.w + g[2]*a2.w + g[3]*a3.w;
        __stcs(oA + d4, o);
        o.x = g[0]*b0.x + g[1]*b1.x + g[2]*b2.x + g[3]*b3.x;
        o.y = g[0]*b0.y + g[1]*b1.y + g[2]*b2.y + g[3]*b3.y;
        o.z = g[0]*b0.z + g[1]*b1.z + g[2]*b2.z + g[3]*b3.z;
        o.w = g[0]*b0.w + g[1]*b1.w + g[2]*b2.w + g[3]*b3.w;
        __stcs(oB + d4, o);
    }

#pragma unroll
    for (int i = 0; i < 4; i++) {
        const float r0 = g[8 + i * 4 + 0];
        const float r1 = g[8 + i * 4 + 1];
        const float r2 = g[8 + i * 4 + 2];
        const float r3 = g[8 + i * 4 + 3];
        const float p  = g[4 + i];
        float4 o;
        o.x = r0*a0.x + r1*a1.x + r2*a2.x + r3*a3.x + p*av.x;
        o.y = r0*a0.y + r1*a1.y + r2*a2.y + r3*a3.y + p*av.y;
        o.z = r0*a0.z + r1*a1.z + r2*a2.z + r3*a3.z + p*av.z;
        o.w = r0*a0.w + r1*a1.w + r2*a2.w + r3*a3.w + p*av.w;
        __stcs(oA + (1 + i) * D4 + d4, o);
        o.x = r0*b0.x + r1*b1.x + r2*b2.x + r3*b3.x + p*bv.x;
        o.y = r0*b0.y + r1*b1.y + r2*b2.y + r3*b3.y + p*bv.y;
        o.z = r0*b0.z + r1*b1.z + r2*b2.z + r3*b3.z + p*bv.z;
        o.w = r0*b0.w + r1*b1.w + r2*b2.w + r3*b3.w + p*bv.w;
        __stcs(oB + (1 + i) * D4 + d4, o);
    }
}

// ---------------------------------------------------------------------------
extern "C" void kernel_launch(void* const* d_in, const int* in_sizes, int n_in,
                              void* d_out, int out_size) {
    const float* H         = (const float*)d_in[0];
    const float* branch_o  = (const float*)d_in[1];
    const float* phi       = (const float*)d_in[2];
    const float* pre_base  = (const float*)d_in[3];
    const float* post_base = (const float*)d_in[4];
    const float* res_base  = (const float*)d_in[5];
    const float* a_pre     = (const float*)d_in[6];
    const float* a_post    = (const float*)d_in[7];
    const float* a_res     = (const float*)d_in[8];
    float* out = (float*)d_out;

    dim3 g1(ND4 / 256, SCHUNKS, BB);
    k_reduce<<<g1, 256>>>((const float4*)H);
    dim3 gA(GA_BLOCKS, BB);
    k_gA<<<gA, 256>>>(phi);
    k_gB<<<1, 128>>>(pre_base, post_base, res_base, a_pre, a_post, a_res);
    const int mix_grid = BB * SCHUNKS * 32;             // 4096 blocks per half
    k_mix<<<mix_grid, 256>>>(H, branch_o, out, 0);      // hot halves first
    k_mix<<<mix_grid, 256>>>(H, branch_o, out, 1);      // cold halves
}